// round 16
// baseline (speedup 1.0000x reference)
#include <cuda_runtime.h>

// RoIAlign2D: features (4,256,96,96) f32, rois (1024,5) f32 -> out (1024,256,7,7) f32
// OUT_SIZE=7, SPATIAL_SCALE=0.0625, SAMPLE_NUM=2
//
// v7: Block = (roi, 32-ch group, y-half). Patch x-stride = 16 (power of 2):
//  - smem 28.75KB -> 7 blocks/SM (~87% occ)
//  - dual-row staging STS = 32 consecutive words = 1 phase
//  - plane stride 193 (odd) -> lane=channel tap LDS is a bank permutation
// Wide rois (xspan > 16) loop over two x-sections (pw 0-3, 4-6); per-section
// tap span <= 3.5*bw_max + 2.5 < 16 always fits. xtab rebuilt per section.

#define CC     256
#define HH     96
#define WW     96
#define SCALE  0.0625f
#define SECTW  16          // patch x stride (section width)
#define PY     12          // max y span per half
#define PSIZE  193         // PY*SECTW + 1 (odd)
#define GROUP  32
#define HW     (HH * WW)
#define NOUTMX 28
#define CPADO  33          // outbuf channel stride (>= GROUP, odd)

#define PATCH_ELEMS  (GROUP * PSIZE)            // 6176
#define OUTBUF_ELEMS (NOUTMX * CPADO)           // 924
#define TAB_FLOATS   (22 * 4)                   // 8 y + 14 x float4 entries
#define SMEM_BYTES   ((TAB_FLOATS + PATCH_ELEMS + OUTBUF_ELEMS) * 4)  // 28752

__global__ __launch_bounds__(256) void roi_align_v7(
    const float* __restrict__ feat,
    const float* __restrict__ rois,
    float* __restrict__ out)
{
    extern __shared__ float smem[];
    float4* ytab   = (float4*)smem;             // [8]
    float4* xtab   = (float4*)smem + 8;         // [14] (per-section, <= 2*npw)
    float*  patch  = smem + TAB_FLOATS;         // [GROUP][PSIZE]
    float*  outbuf = patch + PATCH_ELEMS;       // [NOUTMX][CPADO]

    int blk = blockIdx.x;
    int k   = blk >> 4;                 // roi
    int g   = (blk >> 1) & 7;           // channel group
    int h   = blk & 1;                  // y-half
    int c0  = g * GROUP;

    int phbase = h ? 4 : 0;
    int nrows  = h ? 3 : 4;
    int nout   = nrows * 7;
    int s0     = h ? 8 : 0;
    int ny     = 2 * nrows;

    const float* r = rois + k * 5;
    int   b  = (int)__ldg(r);
    float x1 = __ldg(r + 1) * SCALE;
    float y1 = __ldg(r + 2) * SCALE;
    float x2 = __ldg(r + 3) * SCALE;
    float y2 = __ldg(r + 4) * SCALE;

    float bw = fmaxf(x2 - x1, 1.0f) * (1.0f / 7.0f);
    float bh = fmaxf(y2 - y1, 1.0f) * (1.0f / 7.0f);

    // ---- y extent for this half (once) ----
    float yoff0 = 0.25f + 0.5f * (float)s0;
    float yoffE = 0.25f + 0.5f * (float)(s0 + ny - 1);
    float ycf = fminf(fmaxf(y1 + bh * yoff0, 0.0f), (float)(HH - 1));
    int   ys0 = (int)floorf(ycf);
    float yce = fminf(fmaxf(y1 + bh * yoffE, 0.0f), (float)(HH - 1));
    int yspan = min((int)floorf(yce) + 1, HH - 1) - ys0 + 1;   // <= 12

    // Full-roi x span decides 1 vs 2 sections.
    float xcf = fminf(fmaxf(x1 + bw * 0.25f, 0.0f), (float)(WW - 1));
    float xce = fminf(fmaxf(x1 + bw * 6.75f, 0.0f), (float)(WW - 1));
    int xspan_full = (min((int)floorf(xce) + 1, WW - 1)) - (int)floorf(xcf) + 1;
    int nsec = (xspan_full <= SECTW) ? 1 : 2;

    int tid  = threadIdx.x;
    int w    = tid >> 5;
    int lane = tid & 31;
    int dy   = lane >> 4;       // staging: row within pair
    int dx   = lane & 15;       // staging: column

    // ---- y geometry table (once; threads 0..ny-1) ----
    if (tid < ny) {
        int   s  = s0 + tid;
        float c  = y1 + bh * (0.25f + 0.5f * (float)s);
        bool  v  = (c >= -1.0f) && (c <= (float)HH);
        float cc = fminf(fmaxf(c, 0.0f), (float)(HH - 1));
        float fl = floorf(cc);
        int   lo = (int)fl;
        int   hi = min(lo + 1, HH - 1);
        float fr = cc - fl;
        float4 e;
        e.x = __int_as_float((lo - ys0) * SECTW);
        e.y = __int_as_float((hi - ys0) * SECTW);
        e.z = v ? (1.0f - fr) : 0.0f;
        e.w = v ? fr : 0.0f;
        ytab[tid] = e;
    }

    const float* fbase = feat + (size_t)(b * CC + c0) * HW;
    const float* plane = patch + lane * PSIZE;

    for (int sec = 0; sec < nsec; ++sec) {
        int p0  = (nsec == 1) ? 0 : (sec ? 4 : 0);
        int npw = (nsec == 1) ? 7 : (sec ? 3 : 4);

        // Section x origin from its first sample (monotone clipped coords).
        float xsf = fminf(fmaxf(x1 + bw * ((float)p0 + 0.25f), 0.0f), (float)(WW - 1));
        int   xs0 = (int)floorf(xsf);

        // ---- x geometry table for this section (threads 8..8+2*npw-1) ----
        // Safe vs. previous section: loop-end __syncthreads covers reads.
        if (tid >= 8 && tid < 8 + 2 * npw) {
            int   s  = 2 * p0 + (tid - 8);
            float c  = x1 + bw * (0.25f + 0.5f * (float)s);
            bool  v  = (c >= -1.0f) && (c <= (float)WW);
            float cc = fminf(fmaxf(c, 0.0f), (float)(WW - 1));
            float fl = floorf(cc);
            int   lo = (int)fl;
            int   hi = min(lo + 1, WW - 1);
            float fr = cc - fl;
            float4 e;
            e.x = __int_as_float(lo - xs0);
            e.y = __int_as_float(hi - xs0);
            e.z = v ? (1.0f - fr) : 0.0f;
            e.w = v ? fr : 0.0f;
            xtab[tid - 8] = e;
        }

        // ---- stage section patch ----
        // Warp w stages channels 4w..4w+3; one instr = 2 rows x 16 cols of one
        // channel. STS = 32 consecutive words (1 phase). Clamped dup writes at
        // the edges are never read by compute.
        {
            int col = min(xs0 + dx, WW - 1);
            #pragma unroll
            for (int ci = 0; ci < 4; ++ci) {
                int c = w * 4 + ci;
                const float* gc = fbase + (size_t)c * HW + col;
                float*       pc = patch + c * PSIZE + dx;
                #pragma unroll
                for (int yp = 0; yp < PY; yp += 2) {
                    if (yp < yspan) {
                        int y = min(yp + dy, yspan - 1);
                        pc[y * SECTW] = __ldg(gc + (ys0 + y) * WW);
                    }
                }
            }
        }
        __syncthreads();

        // ---- compute this section's outputs: warp per output, lane=channel ----
        int nout_s = nrows * npw;
        for (int o = w; o < nout_s; o += 8) {
            int ly  = o / npw;
            int pwl = o - ly * npw;
            float4 ya = ytab[2 * ly], yb = ytab[2 * ly + 1];
            float4 xa = xtab[2 * pwl], xb = xtab[2 * pwl + 1];
            float acc = 0.0f;
            #pragma unroll
            for (int sy = 0; sy < 2; ++sy) {
                float4 ye = sy ? yb : ya;
                int rl = __float_as_int(ye.x);
                int rh = __float_as_int(ye.y);
                #pragma unroll
                for (int sx = 0; sx < 2; ++sx) {
                    float4 xe = sx ? xb : xa;
                    int cl = __float_as_int(xe.x);
                    int ch = __float_as_int(xe.y);
                    float tll = plane[rl + cl];
                    float tlh = plane[rl + ch];
                    float thl = plane[rh + cl];
                    float thh = plane[rh + ch];
                    float tlo = xe.z * tll + xe.w * tlh;
                    float thi = xe.z * thl + xe.w * thh;
                    acc += ye.z * tlo + ye.w * thi;
                }
            }
            outbuf[(ly * 7 + p0 + pwl) * CPADO + lane] = acc * 0.25f;
        }
        __syncthreads();   // protects patch/xtab before next section, outbuf before writeback
    }

    // ---- coalesced writeback (stride-33 LDS: conflict-free) ----
    float* obase = out + ((size_t)k * CC + c0) * 49 + phbase * 7;
    for (int e = tid; e < GROUP * NOUTMX; e += 256) {
        int c = e / NOUTMX;
        int o = e - c * NOUTMX;
        if (o < nout)
            obase[c * 49 + o] = outbuf[o * CPADO + c];
    }
}

extern "C" void kernel_launch(void* const* d_in, const int* in_sizes, int n_in,
                              void* d_out, int out_size)
{
    const float* feat = (const float*)d_in[0];
    const float* rois = (const float*)d_in[1];
    float*       out  = (float*)d_out;

    cudaFuncSetAttribute(roi_align_v7,
                         cudaFuncAttributeMaxDynamicSharedMemorySize, SMEM_BYTES);

    int n_rois = in_sizes[1] / 5;   // 1024
    roi_align_v7<<<n_rois * 16, 256, SMEM_BYTES>>>(feat, rois, out);
}